// round 4
// baseline (speedup 1.0000x reference)
#include <cuda_runtime.h>
#include <cstdint>

#define BATCH 8
#define N_PTS 16384
#define M_PTS 1024
#define KS    32
#define CFEAT 64

#define FPS_CL   4                    // cluster size (CTAs per batch)
#define PTS_CTA  (N_PTS / FPS_CL)     // 4096 points per CTA

// ---- output layout (float32): [new_xyz | new_features | indices] ----
#define OUT_XYZ_OFF  0
#define OUT_FEAT_OFF (BATCH * M_PTS * 3)                       // 24576
#define OUT_IDX_OFF  (OUT_FEAT_OFF + BATCH * 256 * M_PTS)      // 2121728

// ---- device scratch ----
__device__ float g_xyzT[BATCH][3][N_PTS];
__device__ float g_featT[BATCH][N_PTS][CFEAT];
__device__ float g_Wt0[72 * 64];
__device__ float g_Wt1[64 * 128];
__device__ float g_Wt2[128 * 256];
__device__ int   g_ball[BATCH][M_PTS][KS];
__device__ float g_center[BATCH][M_PTS][3];

// exact (non-FMA) squared distance, left-to-right sum — must match XLA
__device__ __forceinline__ float sqdist(float dx, float dy, float dz) {
    float d = __fmul_rn(dx, dx);
    d = __fadd_rn(d, __fmul_rn(dy, dy));
    d = __fadd_rn(d, __fmul_rn(dz, dz));
    return d;
}

// ---- packed f32x2 helpers (per-lane IEEE rn, bit-identical to scalar) ----
__device__ __forceinline__ unsigned long long pk2(float a, float b) {
    unsigned long long r;
    asm("mov.b64 %0, {%1, %2};" : "=l"(r) : "f"(a), "f"(b));
    return r;
}
__device__ __forceinline__ void upk2(unsigned long long v, float& a, float& b) {
    asm("mov.b64 {%0, %1}, %2;" : "=f"(a), "=f"(b) : "l"(v));
}
__device__ __forceinline__ unsigned long long add2(unsigned long long a, unsigned long long b) {
    unsigned long long r;
    asm("add.rn.f32x2 %0, %1, %2;" : "=l"(r) : "l"(a), "l"(b));
    return r;
}
__device__ __forceinline__ unsigned long long mul2(unsigned long long a, unsigned long long b) {
    unsigned long long r;
    asm("mul.rn.f32x2 %0, %1, %2;" : "=l"(r) : "l"(a), "l"(b));
    return r;
}

// ---- cluster helpers ----
__device__ __forceinline__ uint32_t smem_u32(const void* p) {
    uint32_t a;
    asm("{ .reg .u64 t; cvta.to.shared.u64 t, %1; cvt.u32.u64 %0, t; }" : "=r"(a) : "l"(p));
    return a;
}
__device__ __forceinline__ uint32_t ctarank() {
    uint32_t r;
    asm("mov.u32 %0, %%cluster_ctarank;" : "=r"(r));
    return r;
}
__device__ __forceinline__ uint32_t mapa_rank(uint32_t addr, uint32_t rank) {
    uint32_t r;
    asm("mapa.shared::cluster.u32 %0, %1, %2;" : "=r"(r) : "r"(addr), "r"(rank));
    return r;
}
__device__ __forceinline__ void st_cl_u32(uint32_t addr, uint32_t v) {
    asm volatile("st.shared::cluster.u32 [%0], %1;" :: "r"(addr), "r"(v) : "memory");
}
__device__ __forceinline__ void arrive_cl(uint32_t mbar) {
    asm volatile("mbarrier.arrive.release.cluster.shared::cluster.b64 _, [%0];"
                 :: "r"(mbar) : "memory");
}
__device__ __forceinline__ void mbar_init(uint32_t mbar, uint32_t cnt) {
    asm volatile("mbarrier.init.shared.b64 [%0], %1;" :: "r"(mbar), "r"(cnt) : "memory");
}
// HW-sleep wait (suspend-time hint), canonical MBARRIER_WAIT_PARITY structure
__device__ __forceinline__ void wait_parity_cl(uint32_t mbar, uint32_t parity) {
    uint32_t done;
    asm volatile(
        "{\n\t.reg .pred p;\n\t"
        "mbarrier.try_wait.parity.acquire.cluster.shared::cta.b64 p, [%1], %2;\n\t"
        "selp.b32 %0, 1, 0, p;\n\t}"
        : "=r"(done) : "r"(mbar), "r"(parity) : "memory");
    if (!done) {
        asm volatile(
            "{\n\t.reg .pred P1;\n\t"
            "WL_%=:\n\t"
            "mbarrier.try_wait.parity.acquire.cluster.shared::cta.b64 P1, [%0], %1, 0x989680;\n\t"
            "@P1 bra.uni WD_%=;\n\t"
            "bra.uni WL_%=;\n\t"
            "WD_%=:\n\t}"
            :: "r"(mbar), "r"(parity) : "memory");
    }
}
__device__ __forceinline__ void cluster_sync_all() {
    asm volatile("barrier.cluster.arrive.aligned;" ::: "memory");
    asm volatile("barrier.cluster.wait.aligned;" ::: "memory");
}

// ======================= prep kernels =======================
__global__ void prep_w_kernel(const float* __restrict__ W0,
                              const float* __restrict__ W1,
                              const float* __restrict__ W2) {
    int id = blockIdx.x * 256 + threadIdx.x;
    if (id < 72 * 64) {
        int c = id >> 6, o = id & 63;
        g_Wt0[id] = (c < 67) ? W0[o * 67 + c] : 0.0f;
    } else if (id < 72 * 64 + 64 * 128) {
        int e = id - 72 * 64;
        int c = e >> 7, o = e & 127;
        g_Wt1[e] = W1[o * 64 + c];
    } else if (id < 72 * 64 + 64 * 128 + 128 * 256) {
        int e = id - 72 * 64 - 64 * 128;
        int c = e >> 8, o = e & 255;
        g_Wt2[e] = W2[o * 128 + c];
    }
}

__global__ void prep_xyz_kernel(const float* __restrict__ xyz) {
    int id = blockIdx.x * 256 + threadIdx.x;
    if (id < BATCH * 3 * N_PTS) {
        int b = id / (3 * N_PTS);
        int r = id % (3 * N_PTS);
        int c = r / N_PTS;
        int n = r % N_PTS;
        g_xyzT[b][c][n] = xyz[(b * N_PTS + n) * 3 + c];
    }
}

__global__ void prep_feat_kernel(const float* __restrict__ f) {
    __shared__ float tile[32][33];
    int b  = blockIdx.z;
    int n0 = blockIdx.x * 32;
    int c0 = blockIdx.y * 32;
    int tx = threadIdx.x;
    for (int i = threadIdx.y; i < 32; i += 8)
        tile[i][tx] = f[((b * CFEAT) + c0 + i) * N_PTS + n0 + tx];
    __syncthreads();
    for (int i = threadIdx.y; i < 32; i += 8)
        g_featT[b][n0 + i][c0 + tx] = tile[tx][i];
}

// ======================= FPS (4-CTA cluster per batch) =======================
// smem float offsets
#define F_SX   0
#define F_SY   (F_SX + PTS_CTA)
#define F_ZP   (F_SY + PTS_CTA)
#define F_RV   (F_ZP + PTS_CTA)          // [2][32]
#define F_RI   (F_RV + 64)               // [2][32]
#define F_MBOX (F_RI + 64)               // [2][4][8] words
#define F_MBAR (F_MBOX + 64)             // 2 floats (8B)
#define FPS_SMEM_FLOATS (F_MBAR + 2)

__global__ __launch_bounds__(1024, 1) __cluster_dims__(FPS_CL, 1, 1)
void fps_kernel(const float* __restrict__ xyz, float* __restrict__ out) {
    extern __shared__ float sm[];
    float*    sx   = sm + F_SX;
    float*    sy   = sm + F_SY;
    float*    zp   = sm + F_ZP;
    unsigned* rv   = (unsigned*)(sm + F_RV);
    unsigned* ri   = (unsigned*)(sm + F_RI);
    volatile unsigned* mbox = (volatile unsigned*)(sm + F_MBOX);

    const uint32_t smbase    = smem_u32(sm);
    const uint32_t mbar_addr = smbase + F_MBAR * 4;
    const uint32_t mbox_addr = smbase + F_MBOX * 4;

    const int b    = blockIdx.x >> 2;
    const uint32_t rank = ctarank();
    const int base = (int)rank * PTS_CTA;
    const int tid  = threadIdx.x;
    const int lane = tid & 31;
    const int wid  = tid >> 5;

    // stage this CTA's slice: local point t (0..4095) = global base + t
    const float* gx = xyz + b * N_PTS * 3;
    for (int t = tid; t < PTS_CTA; t += 1024) {
        int p = base + t;
        float x = gx[3 * p + 0];
        float y = gx[3 * p + 1];
        float z = gx[3 * p + 2];
        sx[t] = x;
        sy[t] = y;
        int k = t >> 10, tt = t & 1023;
        zp[(((k >> 1) * 1024) + tt) * 2 + (k & 1)] = z;
    }
    if (tid == 0) mbar_init(mbar_addr, FPS_CL);
    __syncthreads();
    cluster_sync_all();          // mbarrier + smem visible cluster-wide

    // register cache: 2 packed pairs (pts j*1024+tid, j=0..3)
    unsigned long long xx2[2], yy2[2];
    float dist[4];
#pragma unroll
    for (int j = 0; j < 2; ++j) {
        xx2[j] = pk2(sx[(2 * j) * 1024 + tid], sx[(2 * j + 1) * 1024 + tid]);
        yy2[j] = pk2(sy[(2 * j) * 1024 + tid], sy[(2 * j + 1) * 1024 + tid]);
    }
#pragma unroll
    for (int k = 0; k < 4; ++k) dist[k] = 1e10f;

    // first centroid = global point 0
    float cx = gx[0], cy = gx[1], cz = gx[2];
    int   cidx = 0;

    const unsigned long long* zp64 = (const unsigned long long*)zp;

    for (int it = 0; it < M_PTS; ++it) {
        if (rank == 0 && tid == 0) {
            out[OUT_XYZ_OFF + (b * M_PTS + it) * 3 + 0] = cx;
            out[OUT_XYZ_OFF + (b * M_PTS + it) * 3 + 1] = cy;
            out[OUT_XYZ_OFF + (b * M_PTS + it) * 3 + 2] = cz;
            out[OUT_IDX_OFF + b * M_PTS + it] = (float)cidx;
            g_center[b][it][0] = cx;
            g_center[b][it][1] = cy;
            g_center[b][it][2] = cz;
        }
        if (it == M_PTS - 1) break;

        const unsigned long long ncx = pk2(-cx, -cx);
        const unsigned long long ncy = pk2(-cy, -cy);
        const unsigned long long ncz = pk2(-cz, -cz);

        float mx = -1.0f;
#pragma unroll
        for (int j = 0; j < 2; ++j) {
            unsigned long long zz = zp64[j * 1024 + tid];
            unsigned long long dx = add2(xx2[j], ncx);
            unsigned long long dy = add2(yy2[j], ncy);
            unsigned long long dz = add2(zz,     ncz);
            unsigned long long s  = add2(add2(mul2(dx, dx), mul2(dy, dy)), mul2(dz, dz));
            float d0, d1;
            upk2(s, d0, d1);
            float n0 = fminf(dist[2 * j + 0], d0);
            float n1 = fminf(dist[2 * j + 1], d1);
            dist[2 * j + 0] = n0;
            dist[2 * j + 1] = n1;
            mx = fmaxf(mx, fmaxf(n0, n1));
        }
        int bk = 0;
#pragma unroll
        for (int k = 3; k >= 0; --k)
            if (dist[k] == mx) bk = k;

        // warp argmax (nonneg floats: uint-monotonic), min global index on ties
        const int par = it & 1;
        unsigned mxb  = __float_as_uint(mx);
        unsigned wmax = __reduce_max_sync(0xffffffffu, mxb);
        unsigned cand = (mxb == wmax) ? (unsigned)(base + bk * 1024 + tid) : 0xffffffffu;
        unsigned wi   = __reduce_min_sync(0xffffffffu, cand);
        if (lane == 0) { rv[par * 32 + wid] = wmax; ri[par * 32 + wid] = wi; }
        __syncthreads();

        if (wid == 0) {
            unsigned v = rv[par * 32 + lane], i = ri[par * 32 + lane];
            unsigned bmax = __reduce_max_sync(0xffffffffu, v);
            unsigned c2   = (v == bmax) ? i : 0xffffffffu;
            unsigned gi   = __reduce_min_sync(0xffffffffu, c2);
            if (lane == 0) {
                int pl = (int)gi - base;            // local index in this CTA
                int k  = pl >> 10, tt = pl & 1023;
                unsigned wx = __float_as_uint(sx[pl]);
                unsigned wy = __float_as_uint(sy[pl]);
                unsigned wz = __float_as_uint(zp[(((k >> 1) * 1024) + tt) * 2 + (k & 1)]);
                unsigned recoff = (unsigned)(par * FPS_CL + rank) * 32u;  // bytes
#pragma unroll
                for (int r = 0; r < FPS_CL; ++r) {
                    uint32_t dst = mapa_rank(mbox_addr + recoff, (uint32_t)r);
                    st_cl_u32(dst + 0,  bmax);
                    st_cl_u32(dst + 4,  gi);
                    st_cl_u32(dst + 8,  wx);
                    st_cl_u32(dst + 12, wy);
                    st_cl_u32(dst + 16, wz);
                    arrive_cl(mapa_rank(mbar_addr, (uint32_t)r));
                }
            }
        }

        wait_parity_cl(mbar_addr, (unsigned)par);

        // merge 4 records deterministically (max value, min index)
        {
            const volatile unsigned* rec = mbox + (par * FPS_CL) * 8;
            unsigned bv = rec[0], bi = rec[1], rx = rec[2], ry = rec[3], rz = rec[4];
#pragma unroll
            for (int r = 1; r < FPS_CL; ++r) {
                unsigned v = rec[r * 8 + 0], i = rec[r * 8 + 1];
                if (v > bv || (v == bv && i < bi)) {
                    bv = v; bi = i;
                    rx = rec[r * 8 + 2]; ry = rec[r * 8 + 3]; rz = rec[r * 8 + 4];
                }
            }
            cx = __uint_as_float(rx);
            cy = __uint_as_float(ry);
            cz = __uint_as_float(rz);
            cidx = (int)bi;
        }
    }
    cluster_sync_all();          // no CTA exits while peers may still arrive
}

// ======================= ball query =======================
__global__ __launch_bounds__(128) void ball_kernel() {
    __shared__ int buf[4][32];
    const int wid  = threadIdx.x >> 5;
    const int lane = threadIdx.x & 31;
    const int gw   = blockIdx.x * 4 + wid;
    const int b    = gw >> 10;
    const int m    = gw & 1023;

    const float cx = g_center[b][m][0];
    const float cy = g_center[b][m][1];
    const float cz = g_center[b][m][2];
    const float* __restrict__ px = g_xyzT[b][0];
    const float* __restrict__ py = g_xyzT[b][1];
    const float* __restrict__ pz = g_xyzT[b][2];

    int count = 0;
    for (int n0 = 0; n0 < N_PTS; n0 += 32) {
        int i = n0 + lane;
        float dx = px[i] - cx;
        float dy = py[i] - cy;
        float dz = pz[i] - cz;
        float d  = sqdist(dx, dy, dz);
        bool pr  = (d <= 0.16f);
        unsigned mask = __ballot_sync(0xffffffffu, pr);
        int pos = count + __popc(mask & ((1u << lane) - 1u));
        if (pr && pos < 32) buf[wid][pos] = i;
        count += __popc(mask);
        if (count >= 32) break;
    }
    __syncwarp();
    int first = buf[wid][0];
    int v = (lane < count) ? buf[wid][lane] : first;
    g_ball[b][m][lane] = v;
}

// ======================= fused MLP + maxpool =======================
#define STR 65
#define OFF_XS  0
#define OFF_H1  (OFF_XS + 72 * STR)
#define OFF_H2  (OFF_H1 + 64 * STR)
#define OFF_WS  (OFF_H2 + 128 * STR)
#define OFF_SIDX (OFF_WS + 8 * 256)
#define OFF_SCTR (OFF_SIDX + 64)
#define MLP_SMEM_FLOATS (OFF_SCTR + 8)

template <int CIN, int COUT, bool LAST>
__device__ __forceinline__ void mlp_layer(
    const float* __restrict__ Wt,
    const float* __restrict__ bias,
    const float* __restrict__ scale,
    const float* __restrict__ shift,
    const float* Xin, float* Xout, float* Ws,
    float* __restrict__ outF, int b, int m0)
{
    const int tid = threadIdx.x;
    const int kk  = tid & 7;
    const int ro  = tid >> 3;
    constexpr int R = COUT / 32;

    float acc[R][8];
#pragma unroll
    for (int i = 0; i < R; ++i)
#pragma unroll
        for (int j = 0; j < 8; ++j) acc[i][j] = 0.0f;

    for (int ct = 0; ct < CIN; ct += 8) {
        __syncthreads();
        for (int e = tid; e < 8 * COUT; e += 256) Ws[e] = Wt[ct * COUT + e];
        __syncthreads();
#pragma unroll
        for (int cl = 0; cl < 8; ++cl) {
            float xv[8];
#pragma unroll
            for (int j = 0; j < 8; ++j) xv[j] = Xin[(ct + cl) * STR + kk + 8 * j];
#pragma unroll
            for (int i = 0; i < R; ++i) {
                float wv = Ws[cl * COUT + ro + 32 * i];
#pragma unroll
                for (int j = 0; j < 8; ++j) acc[i][j] = fmaf(wv, xv[j], acc[i][j]);
            }
        }
    }
    __syncthreads();

#pragma unroll
    for (int i = 0; i < R; ++i) {
        int o = ro + 32 * i;
        float bb = bias[o], ss = scale[o], tt = shift[o];
        if constexpr (!LAST) {
#pragma unroll
            for (int j = 0; j < 8; ++j) {
                float v = (acc[i][j] + bb) * ss + tt;
                Xout[o * STR + kk + 8 * j] = fmaxf(v, 0.0f);
            }
        } else {
            float vA = 0.0f, vB = 0.0f;
#pragma unroll
            for (int j = 0; j < 8; ++j) {
                float v = fmaxf((acc[i][j] + bb) * ss + tt, 0.0f);
                if (j < 4) vA = fmaxf(vA, v); else vB = fmaxf(vB, v);
            }
#pragma unroll
            for (int d = 1; d < 8; d <<= 1) {
                vA = fmaxf(vA, __shfl_xor_sync(0xffffffffu, vA, d));
                vB = fmaxf(vB, __shfl_xor_sync(0xffffffffu, vB, d));
            }
            if (kk == 0) {
                outF[(b * 256 + o) * M_PTS + m0]     = vA;
                outF[(b * 256 + o) * M_PTS + m0 + 1] = vB;
            }
        }
    }
    if constexpr (!LAST) __syncthreads();
}

__global__ __launch_bounds__(256, 2) void mlp_kernel(
    const float* __restrict__ b0, const float* __restrict__ s0, const float* __restrict__ t0,
    const float* __restrict__ b1, const float* __restrict__ s1, const float* __restrict__ t1,
    const float* __restrict__ b2, const float* __restrict__ s2, const float* __restrict__ t2,
    float* __restrict__ outF)
{
    extern __shared__ float sm[];
    const int tid = threadIdx.x;
    const int b   = blockIdx.y;
    const int m0  = blockIdx.x * 2;

    int*   sIdx = (int*)(sm + OFF_SIDX);
    float* sCtr = sm + OFF_SCTR;

    if (tid < 64) sIdx[tid] = g_ball[b][m0 + (tid >> 5)][tid & 31];
    if (tid < 6)  sCtr[tid] = g_center[b][m0 + tid / 3][tid % 3];
    __syncthreads();

    {
        int col  = tid >> 2;
        int part = tid & 3;
        int p    = sIdx[col];
        int half = col >> 5;
        float cx = sCtr[half * 3 + 0];
        float cy = sCtr[half * 3 + 1];
        float cz = sCtr[half * 3 + 2];
        const float* fp = &g_featT[b][p][0];
#pragma unroll
        for (int jj = 0; jj < 18; ++jj) {
            int r = part * 18 + jj;
            float v;
            if (r == 0)      v = g_xyzT[b][0][p] - cx;
            else if (r == 1) v = g_xyzT[b][1][p] - cy;
            else if (r == 2) v = g_xyzT[b][2][p] - cz;
            else if (r < 67) v = fp[r - 3];
            else             v = 0.0f;
            sm[OFF_XS + r * STR + col] = v;
        }
    }
    __syncthreads();

    mlp_layer<72, 64, false>(g_Wt0, b0, s0, t0, sm + OFF_XS, sm + OFF_H1, sm + OFF_WS, nullptr, b, m0);
    mlp_layer<64, 128, false>(g_Wt1, b1, s1, t1, sm + OFF_H1, sm + OFF_H2, sm + OFF_WS, nullptr, b, m0);
    mlp_layer<128, 256, true>(g_Wt2, b2, s2, t2, sm + OFF_H2, nullptr,     sm + OFF_WS, outF, b, m0);
}

// ======================= launch =======================
extern "C" void kernel_launch(void* const* d_in, const int* in_sizes, int n_in,
                              void* d_out, int out_size) {
    const float* xyz  = (const float*)d_in[0];
    const float* feat = (const float*)d_in[1];
    const float* W0 = (const float*)d_in[2];
    const float* b0 = (const float*)d_in[3];
    const float* s0 = (const float*)d_in[4];
    const float* t0 = (const float*)d_in[5];
    const float* W1 = (const float*)d_in[6];
    const float* b1 = (const float*)d_in[7];
    const float* s1 = (const float*)d_in[8];
    const float* t1 = (const float*)d_in[9];
    const float* W2 = (const float*)d_in[10];
    const float* b2 = (const float*)d_in[11];
    const float* s2 = (const float*)d_in[12];
    const float* t2 = (const float*)d_in[13];
    float* out = (float*)d_out;

    const int fps_smem = FPS_SMEM_FLOATS * sizeof(float);
    const int mlp_smem = MLP_SMEM_FLOATS * sizeof(float);
    cudaFuncSetAttribute(fps_kernel, cudaFuncAttributeMaxDynamicSharedMemorySize, fps_smem);
    cudaFuncSetAttribute(mlp_kernel, cudaFuncAttributeMaxDynamicSharedMemorySize, mlp_smem);

    prep_w_kernel<<<178, 256>>>(W0, W1, W2);
    prep_xyz_kernel<<<1536, 256>>>(xyz);
    prep_feat_kernel<<<dim3(N_PTS / 32, CFEAT / 32, BATCH), dim3(32, 8)>>>(feat);

    fps_kernel<<<BATCH * FPS_CL, 1024, fps_smem>>>(xyz, out);
    ball_kernel<<<(BATCH * M_PTS) / 4, 128>>>();
    mlp_kernel<<<dim3(M_PTS / 2, BATCH), 256, mlp_smem>>>(
        b0, s0, t0, b1, s1, t1, b2, s2, t2, out + OUT_FEAT_OFF);
}

// round 6
// speedup vs baseline: 1.1894x; 1.1894x over previous
#include <cuda_runtime.h>

#define BATCH 8
#define N_PTS 16384
#define M_PTS 1024
#define KS    32
#define CFEAT 64

// ---- output layout (float32): [new_xyz | new_features | indices] ----
#define OUT_XYZ_OFF  0
#define OUT_FEAT_OFF (BATCH * M_PTS * 3)                       // 24576
#define OUT_IDX_OFF  (OUT_FEAT_OFF + BATCH * 256 * M_PTS)      // 2121728

// ---- device scratch ----
__device__ float g_xyzT[BATCH][3][N_PTS];
__device__ float g_featT[BATCH][N_PTS][CFEAT];
__device__ float g_Wt0[72 * 64];
__device__ float g_Wt1[64 * 128];
__device__ float g_Wt2[128 * 256];
__device__ int   g_ball[BATCH][M_PTS][KS];
__device__ float g_center[BATCH][M_PTS][3];

// exact (non-FMA) squared distance, left-to-right sum — must match XLA
__device__ __forceinline__ float sqdist(float dx, float dy, float dz) {
    float d = __fmul_rn(dx, dx);
    d = __fadd_rn(d, __fmul_rn(dy, dy));
    d = __fadd_rn(d, __fmul_rn(dz, dz));
    return d;
}

// ---- packed f32x2 helpers (per-lane IEEE rn, bit-identical to scalar) ----
__device__ __forceinline__ unsigned long long pk2(float a, float b) {
    unsigned long long r;
    asm("mov.b64 %0, {%1, %2};" : "=l"(r) : "f"(a), "f"(b));
    return r;
}
__device__ __forceinline__ void upk2(unsigned long long v, float& a, float& b) {
    asm("mov.b64 {%0, %1}, %2;" : "=f"(a), "=f"(b) : "l"(v));
}
__device__ __forceinline__ unsigned long long add2(unsigned long long a, unsigned long long b) {
    unsigned long long r;
    asm("add.rn.f32x2 %0, %1, %2;" : "=l"(r) : "l"(a), "l"(b));
    return r;
}
__device__ __forceinline__ unsigned long long mul2(unsigned long long a, unsigned long long b) {
    unsigned long long r;
    asm("mul.rn.f32x2 %0, %1, %2;" : "=l"(r) : "l"(a), "l"(b));
    return r;
}

// ======================= prep kernels =======================
__global__ void prep_w_kernel(const float* __restrict__ W0,
                              const float* __restrict__ W1,
                              const float* __restrict__ W2) {
    int id = blockIdx.x * 256 + threadIdx.x;
    if (id < 72 * 64) {
        int c = id >> 6, o = id & 63;
        g_Wt0[id] = (c < 67) ? W0[o * 67 + c] : 0.0f;
    } else if (id < 72 * 64 + 64 * 128) {
        int e = id - 72 * 64;
        int c = e >> 7, o = e & 127;
        g_Wt1[e] = W1[o * 64 + c];
    } else if (id < 72 * 64 + 64 * 128 + 128 * 256) {
        int e = id - 72 * 64 - 64 * 128;
        int c = e >> 8, o = e & 255;
        g_Wt2[e] = W2[o * 128 + c];
    }
}

__global__ void prep_xyz_kernel(const float* __restrict__ xyz) {
    int id = blockIdx.x * 256 + threadIdx.x;
    if (id < BATCH * 3 * N_PTS) {
        int b = id / (3 * N_PTS);
        int r = id % (3 * N_PTS);
        int c = r / N_PTS;
        int n = r % N_PTS;
        g_xyzT[b][c][n] = xyz[(b * N_PTS + n) * 3 + c];
    }
}

__global__ void prep_feat_kernel(const float* __restrict__ f) {
    __shared__ float tile[32][33];
    int b  = blockIdx.z;
    int n0 = blockIdx.x * 32;
    int c0 = blockIdx.y * 32;
    int tx = threadIdx.x;
    for (int i = threadIdx.y; i < 32; i += 8)
        tile[i][tx] = f[((b * CFEAT) + c0 + i) * N_PTS + n0 + tx];
    __syncthreads();
    for (int i = threadIdx.y; i < 32; i += 8)
        g_featT[b][n0 + i][c0 + tx] = tile[tx][i];
}

// ======================= FPS (R2 version — known good) =======================
// one block per batch; x,y cached in packed registers; z in paired smem;
// packed f32x2 math; REDUX-based argmax with lowest-index tie-break.
__global__ __launch_bounds__(1024, 1) void fps_kernel(const float* __restrict__ xyz,
                                                      float* __restrict__ out) {
    extern __shared__ float sm[];
    float* sx = sm;
    float* sy = sm + N_PTS;
    float* zp = sm + 2 * N_PTS;
    unsigned* rv   = (unsigned*)(sm + 3 * N_PTS);
    unsigned* ri   = rv + 32;
    float*    bc   = (float*)(ri + 32);
    int*      bidx = (int*)(bc + 3);

    const int b    = blockIdx.x;
    const int tid  = threadIdx.x;
    const int lane = tid & 31;
    const int wid  = tid >> 5;

    const float* gx = xyz + b * N_PTS * 3;
    for (int t = tid; t < N_PTS; t += 1024) {
        float x = gx[3 * t + 0];
        float y = gx[3 * t + 1];
        float z = gx[3 * t + 2];
        sx[t] = x;
        sy[t] = y;
        int k = t >> 10, tt = t & 1023;
        zp[(((k >> 1) * 1024) + tt) * 2 + (k & 1)] = z;
    }
    __syncthreads();

    unsigned long long xx2[8], yy2[8];
    float dist[16];
#pragma unroll
    for (int j = 0; j < 8; ++j) {
        xx2[j] = pk2(sx[(2 * j) * 1024 + tid], sx[(2 * j + 1) * 1024 + tid]);
        yy2[j] = pk2(sy[(2 * j) * 1024 + tid], sy[(2 * j + 1) * 1024 + tid]);
    }
#pragma unroll
    for (int k = 0; k < 16; ++k) dist[k] = 1e10f;

    if (tid == 0) {
        bc[0] = sx[0];
        bc[1] = sy[0];
        bc[2] = zp[0];
        *bidx = 0;
    }
    __syncthreads();

    const unsigned long long* zp64 = (const unsigned long long*)zp;

    for (int it = 0; it < M_PTS; ++it) {
        const float cx = bc[0], cy = bc[1], cz = bc[2];
        if (tid == 0) {
            int cur = *bidx;
            out[OUT_XYZ_OFF + (b * M_PTS + it) * 3 + 0] = cx;
            out[OUT_XYZ_OFF + (b * M_PTS + it) * 3 + 1] = cy;
            out[OUT_XYZ_OFF + (b * M_PTS + it) * 3 + 2] = cz;
            out[OUT_IDX_OFF + b * M_PTS + it] = (float)cur;
            g_center[b][it][0] = cx;
            g_center[b][it][1] = cy;
            g_center[b][it][2] = cz;
        }

        const unsigned long long ncx = pk2(-cx, -cx);
        const unsigned long long ncy = pk2(-cy, -cy);
        const unsigned long long ncz = pk2(-cz, -cz);

        float mx = -1.0f;
#pragma unroll
        for (int j = 0; j < 8; ++j) {
            unsigned long long zz = zp64[j * 1024 + tid];
            unsigned long long dx = add2(xx2[j], ncx);
            unsigned long long dy = add2(yy2[j], ncy);
            unsigned long long dz = add2(zz,     ncz);
            unsigned long long s  = add2(add2(mul2(dx, dx), mul2(dy, dy)), mul2(dz, dz));
            float d0, d1;
            upk2(s, d0, d1);
            float n0 = fminf(dist[2 * j + 0], d0);
            float n1 = fminf(dist[2 * j + 1], d1);
            dist[2 * j + 0] = n0;
            dist[2 * j + 1] = n1;
            mx = fmaxf(mx, fmaxf(n0, n1));
        }

        int bk = 0;
#pragma unroll
        for (int k = 15; k >= 0; --k)
            if (dist[k] == mx) bk = k;

        unsigned mxb  = __float_as_uint(mx);
        unsigned wmax = __reduce_max_sync(0xffffffffu, mxb);
        unsigned cand = (mxb == wmax) ? (unsigned)(bk * 1024 + tid) : 0xffffffffu;
        unsigned wi   = __reduce_min_sync(0xffffffffu, cand);
        if (lane == 0) { rv[wid] = wmax; ri[wid] = wi; }
        __syncthreads();

        if (wid == 0) {
            unsigned v = rv[lane], i = ri[lane];
            unsigned bmax = __reduce_max_sync(0xffffffffu, v);
            unsigned c2   = (v == bmax) ? i : 0xffffffffu;
            unsigned gi   = __reduce_min_sync(0xffffffffu, c2);
            if (lane == 0) {
                int p = (int)gi;
                int k = p >> 10, tt = p & 1023;
                bc[0] = sx[p];
                bc[1] = sy[p];
                bc[2] = zp[(((k >> 1) * 1024) + tt) * 2 + (k & 1)];
                *bidx = p;
            }
        }
        __syncthreads();
    }
}

// ======================= ball query =======================
__global__ __launch_bounds__(128) void ball_kernel() {
    __shared__ int buf[4][32];
    const int wid  = threadIdx.x >> 5;
    const int lane = threadIdx.x & 31;
    const int gw   = blockIdx.x * 4 + wid;
    const int b    = gw >> 10;
    const int m    = gw & 1023;

    const float cx = g_center[b][m][0];
    const float cy = g_center[b][m][1];
    const float cz = g_center[b][m][2];
    const float* __restrict__ px = g_xyzT[b][0];
    const float* __restrict__ py = g_xyzT[b][1];
    const float* __restrict__ pz = g_xyzT[b][2];

    int count = 0;
    for (int n0 = 0; n0 < N_PTS; n0 += 32) {
        int i = n0 + lane;
        float dx = px[i] - cx;
        float dy = py[i] - cy;
        float dz = pz[i] - cz;
        float d  = sqdist(dx, dy, dz);
        bool pr  = (d <= 0.16f);
        unsigned mask = __ballot_sync(0xffffffffu, pr);
        int pos = count + __popc(mask & ((1u << lane) - 1u));
        if (pr && pos < 32) buf[wid][pos] = i;
        count += __popc(mask);
        if (count >= 32) break;
    }
    __syncwarp();
    int first = buf[wid][0];
    int v = (lane < count) ? buf[wid][lane] : first;
    g_ball[b][m][lane] = v;
}

// ======================= fused MLP + maxpool (vectorized LDS) =======================
// column index  = kk*8 + j  (kk = tid&7, j = 0..7)  -> contiguous LDS.128 activations
// output row    = ro*R + i  (ro = tid>>3, i = 0..R-1) -> contiguous vector weight loads
#define STR 68
#define OFF_XS  0
#define OFF_H1  (OFF_XS + 72 * STR)
#define OFF_H2  (OFF_H1 + 64 * STR)
#define OFF_WS  (OFF_H2 + 128 * STR)
#define OFF_SIDX (OFF_WS + 8 * 256)
#define OFF_SCTR (OFF_SIDX + 64)
#define MLP_SMEM_FLOATS (OFF_SCTR + 8)

template <int CIN, int COUT, bool LAST>
__device__ __forceinline__ void mlp_layer(
    const float* __restrict__ Wt,     // [CIN][COUT] global
    const float* __restrict__ bias,
    const float* __restrict__ scale,
    const float* __restrict__ shift,
    const float* Xin, float* Xout, float* Ws,
    float* __restrict__ outF, int b, int m0)
{
    const int tid = threadIdx.x;
    const int kk  = tid & 7;
    const int ro  = tid >> 3;
    constexpr int R = COUT / 32;

    float acc[R][8];
#pragma unroll
    for (int i = 0; i < R; ++i)
#pragma unroll
        for (int j = 0; j < 8; ++j) acc[i][j] = 0.0f;

    for (int ct = 0; ct < CIN; ct += 8) {
        __syncthreads();
        for (int e = tid; e < 8 * COUT; e += 256) Ws[e] = Wt[ct * COUT + e];
        __syncthreads();
#pragma unroll
        for (int cl = 0; cl < 8; ++cl) {
            float xv[8];
            *(float4*)&xv[0] = *(const float4*)&Xin[(ct + cl) * STR + kk * 8];
            *(float4*)&xv[4] = *(const float4*)&Xin[(ct + cl) * STR + kk * 8 + 4];
            float wv[R];
            if constexpr (R == 2) {
                *(float2*)&wv[0] = *(const float2*)&Ws[cl * COUT + ro * 2];
            } else if constexpr (R == 4) {
                *(float4*)&wv[0] = *(const float4*)&Ws[cl * COUT + ro * 4];
            } else {
                *(float4*)&wv[0] = *(const float4*)&Ws[cl * COUT + ro * 8];
                *(float4*)&wv[4] = *(const float4*)&Ws[cl * COUT + ro * 8 + 4];
            }
#pragma unroll
            for (int i = 0; i < R; ++i)
#pragma unroll
                for (int j = 0; j < 8; ++j)
                    acc[i][j] = fmaf(wv[i], xv[j], acc[i][j]);
        }
    }
    __syncthreads();

#pragma unroll
    for (int i = 0; i < R; ++i) {
        int o = ro * R + i;
        float bb = bias[o], ss = scale[o], tt = shift[o];
        if constexpr (!LAST) {
            float y[8];
#pragma unroll
            for (int j = 0; j < 8; ++j)
                y[j] = fmaxf((acc[i][j] + bb) * ss + tt, 0.0f);
            *(float4*)&Xout[o * STR + kk * 8]     = *(float4*)&y[0];
            *(float4*)&Xout[o * STR + kk * 8 + 4] = *(float4*)&y[4];
        } else {
            // columns kk*8+j: kk<4 -> centroid m0, kk>=4 -> m0+1
            float v = 0.0f;
#pragma unroll
            for (int j = 0; j < 8; ++j)
                v = fmaxf(v, fmaxf((acc[i][j] + bb) * ss + tt, 0.0f));
            v = fmaxf(v, __shfl_xor_sync(0xffffffffu, v, 1));
            v = fmaxf(v, __shfl_xor_sync(0xffffffffu, v, 2));
            if ((tid & 3) == 0) {
                int which = (tid & 4) ? 1 : 0;
                outF[(b * 256 + o) * M_PTS + m0 + which] = v;
            }
        }
    }
    if constexpr (!LAST) __syncthreads();
}

__global__ __launch_bounds__(256, 2) void mlp_kernel(
    const float* __restrict__ b0, const float* __restrict__ s0, const float* __restrict__ t0,
    const float* __restrict__ b1, const float* __restrict__ s1, const float* __restrict__ t1,
    const float* __restrict__ b2, const float* __restrict__ s2, const float* __restrict__ t2,
    float* __restrict__ outF)
{
    extern __shared__ float sm[];
    const int tid = threadIdx.x;
    const int b   = blockIdx.y;
    const int m0  = blockIdx.x * 2;

    int*   sIdx = (int*)(sm + OFF_SIDX);
    float* sCtr = sm + OFF_SCTR;

    if (tid < 64) sIdx[tid] = g_ball[b][m0 + (tid >> 5)][tid & 31];
    if (tid < 6)  sCtr[tid] = g_center[b][m0 + tid / 3][tid % 3];
    __syncthreads();

    {
        int col  = tid >> 2;
        int part = tid & 3;
        int p    = sIdx[col];
        int half = col >> 5;
        float cx = sCtr[half * 3 + 0];
        float cy = sCtr[half * 3 + 1];
        float cz = sCtr[half * 3 + 2];
        const float* fp = &g_featT[b][p][0];
#pragma unroll
        for (int jj = 0; jj < 18; ++jj) {
            int r = part * 18 + jj;
            float v;
            if (r == 0)      v = g_xyzT[b][0][p] - cx;
            else if (r == 1) v = g_xyzT[b][1][p] - cy;
            else if (r == 2) v = g_xyzT[b][2][p] - cz;
            else if (r < 67) v = fp[r - 3];
            else             v = 0.0f;
            sm[OFF_XS + r * STR + col] = v;
        }
    }
    __syncthreads();

    mlp_layer<72, 64, false>(g_Wt0, b0, s0, t0, sm + OFF_XS, sm + OFF_H1, sm + OFF_WS, nullptr, b, m0);
    mlp_layer<64, 128, false>(g_Wt1, b1, s1, t1, sm + OFF_H1, sm + OFF_H2, sm + OFF_WS, nullptr, b, m0);
    mlp_layer<128, 256, true>(g_Wt2, b2, s2, t2, sm + OFF_H2, nullptr,     sm + OFF_WS, outF, b, m0);
}

// ======================= launch =======================
extern "C" void kernel_launch(void* const* d_in, const int* in_sizes, int n_in,
                              void* d_out, int out_size) {
    const float* xyz  = (const float*)d_in[0];
    const float* feat = (const float*)d_in[1];
    const float* W0 = (const float*)d_in[2];
    const float* b0 = (const float*)d_in[3];
    const float* s0 = (const float*)d_in[4];
    const float* t0 = (const float*)d_in[5];
    const float* W1 = (const float*)d_in[6];
    const float* b1 = (const float*)d_in[7];
    const float* s1 = (const float*)d_in[8];
    const float* t1 = (const float*)d_in[9];
    const float* W2 = (const float*)d_in[10];
    const float* b2 = (const float*)d_in[11];
    const float* s2 = (const float*)d_in[12];
    const float* t2 = (const float*)d_in[13];
    float* out = (float*)d_out;

    const int fps_smem = (3 * N_PTS + 80) * sizeof(float);
    const int mlp_smem = MLP_SMEM_FLOATS * sizeof(float);
    cudaFuncSetAttribute(fps_kernel, cudaFuncAttributeMaxDynamicSharedMemorySize, fps_smem);
    cudaFuncSetAttribute(mlp_kernel, cudaFuncAttributeMaxDynamicSharedMemorySize, mlp_smem);

    prep_w_kernel<<<178, 256>>>(W0, W1, W2);
    prep_xyz_kernel<<<1536, 256>>>(xyz);
    prep_feat_kernel<<<dim3(N_PTS / 32, CFEAT / 32, BATCH), dim3(32, 8)>>>(feat);

    fps_kernel<<<BATCH, 1024, fps_smem>>>(xyz, out);
    ball_kernel<<<(BATCH * M_PTS) / 4, 128>>>();
    mlp_kernel<<<dim3(M_PTS / 2, BATCH), 256, mlp_smem>>>(
        b0, s0, t0, b1, s1, t1, b2, s2, t2, out + OUT_FEAT_OFF);
}

// round 7
// speedup vs baseline: 1.2533x; 1.0537x over previous
#include <cuda_runtime.h>

#define BATCH 8
#define N_PTS 16384
#define M_PTS 1024
#define KS    32
#define CFEAT 64

// ---- output layout (float32): [new_xyz | new_features | indices] ----
#define OUT_XYZ_OFF  0
#define OUT_FEAT_OFF (BATCH * M_PTS * 3)                       // 24576
#define OUT_IDX_OFF  (OUT_FEAT_OFF + BATCH * 256 * M_PTS)      // 2121728

// ---- device scratch ----
__device__ float g_xyzT[BATCH][3][N_PTS];
__device__ float g_featT[BATCH][N_PTS][CFEAT];
__device__ float g_Wt0[72 * 64];
__device__ float g_Wt1[64 * 128];
__device__ float g_Wt2[128 * 256];
__device__ int   g_ball[BATCH][M_PTS][KS];
__device__ float g_center[BATCH][M_PTS][3];

// exact (non-FMA) squared distance, left-to-right sum — must match XLA
__device__ __forceinline__ float sqdist(float dx, float dy, float dz) {
    float d = __fmul_rn(dx, dx);
    d = __fadd_rn(d, __fmul_rn(dy, dy));
    d = __fadd_rn(d, __fmul_rn(dz, dz));
    return d;
}

// ---- packed f32x2 helpers (per-lane IEEE rn, bit-identical to scalar) ----
__device__ __forceinline__ unsigned long long pk2(float a, float b) {
    unsigned long long r;
    asm("mov.b64 %0, {%1, %2};" : "=l"(r) : "f"(a), "f"(b));
    return r;
}
__device__ __forceinline__ void upk2(unsigned long long v, float& a, float& b) {
    asm("mov.b64 {%0, %1}, %2;" : "=f"(a), "=f"(b) : "l"(v));
}
__device__ __forceinline__ unsigned long long add2(unsigned long long a, unsigned long long b) {
    unsigned long long r;
    asm("add.rn.f32x2 %0, %1, %2;" : "=l"(r) : "l"(a), "l"(b));
    return r;
}
__device__ __forceinline__ unsigned long long mul2(unsigned long long a, unsigned long long b) {
    unsigned long long r;
    asm("mul.rn.f32x2 %0, %1, %2;" : "=l"(r) : "l"(a), "l"(b));
    return r;
}

// ======================= prep kernels =======================
__global__ void prep_w_kernel(const float* __restrict__ W0,
                              const float* __restrict__ W1,
                              const float* __restrict__ W2) {
    int id = blockIdx.x * 256 + threadIdx.x;
    if (id < 72 * 64) {
        int c = id >> 6, o = id & 63;
        g_Wt0[id] = (c < 67) ? W0[o * 67 + c] : 0.0f;
    } else if (id < 72 * 64 + 64 * 128) {
        int e = id - 72 * 64;
        int c = e >> 7, o = e & 127;
        g_Wt1[e] = W1[o * 64 + c];
    } else if (id < 72 * 64 + 64 * 128 + 128 * 256) {
        int e = id - 72 * 64 - 64 * 128;
        int c = e >> 8, o = e & 255;
        g_Wt2[e] = W2[o * 128 + c];
    }
}

__global__ void prep_xyz_kernel(const float* __restrict__ xyz) {
    int id = blockIdx.x * 256 + threadIdx.x;
    if (id < BATCH * 3 * N_PTS) {
        int b = id / (3 * N_PTS);
        int r = id % (3 * N_PTS);
        int c = r / N_PTS;
        int n = r % N_PTS;
        g_xyzT[b][c][n] = xyz[(b * N_PTS + n) * 3 + c];
    }
}

__global__ void prep_feat_kernel(const float* __restrict__ f) {
    __shared__ float tile[32][33];
    int b  = blockIdx.z;
    int n0 = blockIdx.x * 32;
    int c0 = blockIdx.y * 32;
    int tx = threadIdx.x;
    for (int i = threadIdx.y; i < 32; i += 8)
        tile[i][tx] = f[((b * CFEAT) + c0 + i) * N_PTS + n0 + tx];
    __syncthreads();
    for (int i = threadIdx.y; i < 32; i += 8)
        g_featT[b][n0 + i][c0 + tx] = tile[tx][i];
}

// ======================= FPS =======================
// one block per batch; x,y cached in packed registers; z in paired smem;
// SINGLE barrier per iteration: warp leaders post (max,idx) to parity-indexed
// smem, then EVERY warp redundantly reduces the 32 records and looks up the
// winner's coords locally (no second barrier, no serial broadcast chain).
__global__ __launch_bounds__(1024, 1) void fps_kernel(const float* __restrict__ xyz,
                                                      float* __restrict__ out) {
    extern __shared__ float sm[];
    float* sx = sm;
    float* sy = sm + N_PTS;
    float* zp = sm + 2 * N_PTS;
    unsigned* rv = (unsigned*)(sm + 3 * N_PTS);   // [2][32]
    unsigned* ri = rv + 64;                        // [2][32]

    const int b    = blockIdx.x;
    const int tid  = threadIdx.x;
    const int lane = tid & 31;
    const int wid  = tid >> 5;

    const float* gx = xyz + b * N_PTS * 3;
    for (int t = tid; t < N_PTS; t += 1024) {
        float x = gx[3 * t + 0];
        float y = gx[3 * t + 1];
        float z = gx[3 * t + 2];
        sx[t] = x;
        sy[t] = y;
        int k = t >> 10, tt = t & 1023;
        zp[(((k >> 1) * 1024) + tt) * 2 + (k & 1)] = z;
    }
    __syncthreads();

    unsigned long long xx2[8], yy2[8];
    float dist[16];
#pragma unroll
    for (int j = 0; j < 8; ++j) {
        xx2[j] = pk2(sx[(2 * j) * 1024 + tid], sx[(2 * j + 1) * 1024 + tid]);
        yy2[j] = pk2(sy[(2 * j) * 1024 + tid], sy[(2 * j + 1) * 1024 + tid]);
    }
#pragma unroll
    for (int k = 0; k < 16; ++k) dist[k] = 1e10f;

    // current centroid lives in registers of EVERY thread
    float cx = sx[0], cy = sy[0], cz = zp[0];
    int   cidx = 0;

    const unsigned long long* zp64 = (const unsigned long long*)zp;

    for (int it = 0; it < M_PTS; ++it) {
        if (tid == 0) {
            out[OUT_XYZ_OFF + (b * M_PTS + it) * 3 + 0] = cx;
            out[OUT_XYZ_OFF + (b * M_PTS + it) * 3 + 1] = cy;
            out[OUT_XYZ_OFF + (b * M_PTS + it) * 3 + 2] = cz;
            out[OUT_IDX_OFF + b * M_PTS + it] = (float)cidx;
            g_center[b][it][0] = cx;
            g_center[b][it][1] = cy;
            g_center[b][it][2] = cz;
        }
        if (it == M_PTS - 1) break;

        const unsigned long long ncx = pk2(-cx, -cx);
        const unsigned long long ncy = pk2(-cy, -cy);
        const unsigned long long ncz = pk2(-cz, -cz);

        float mx = -1.0f;
#pragma unroll
        for (int j = 0; j < 8; ++j) {
            unsigned long long zz = zp64[j * 1024 + tid];
            unsigned long long dx = add2(xx2[j], ncx);
            unsigned long long dy = add2(yy2[j], ncy);
            unsigned long long dz = add2(zz,     ncz);
            unsigned long long s  = add2(add2(mul2(dx, dx), mul2(dy, dy)), mul2(dz, dz));
            float d0, d1;
            upk2(s, d0, d1);
            float n0 = fminf(dist[2 * j + 0], d0);
            float n1 = fminf(dist[2 * j + 1], d1);
            dist[2 * j + 0] = n0;
            dist[2 * j + 1] = n1;
            mx = fmaxf(mx, fmaxf(n0, n1));
        }

        int bk = 0;
#pragma unroll
        for (int k = 15; k >= 0; --k)
            if (dist[k] == mx) bk = k;

        const int par = (it & 1) * 32;
        unsigned mxb  = __float_as_uint(mx);
        unsigned wmax = __reduce_max_sync(0xffffffffu, mxb);
        unsigned cand = (mxb == wmax) ? (unsigned)(bk * 1024 + tid) : 0xffffffffu;
        unsigned wi   = __reduce_min_sync(0xffffffffu, cand);
        if (lane == 0) { rv[par + wid] = wmax; ri[par + wid] = wi; }
        __syncthreads();

        // every warp redundantly reduces the 32 per-warp records
        unsigned v    = rv[par + lane];
        unsigned i    = ri[par + lane];
        unsigned bmax = __reduce_max_sync(0xffffffffu, v);
        unsigned c2   = (v == bmax) ? i : 0xffffffffu;
        unsigned gi   = __reduce_min_sync(0xffffffffu, c2);
        {
            int p = (int)gi;
            int k = p >> 10, tt = p & 1023;
            cx = sx[p];
            cy = sy[p];
            cz = zp[(((k >> 1) * 1024) + tt) * 2 + (k & 1)];
            cidx = p;
        }
    }
}

// ======================= ball query =======================
__global__ __launch_bounds__(128) void ball_kernel() {
    __shared__ int buf[4][32];
    const int wid  = threadIdx.x >> 5;
    const int lane = threadIdx.x & 31;
    const int gw   = blockIdx.x * 4 + wid;
    const int b    = gw >> 10;
    const int m    = gw & 1023;

    const float cx = g_center[b][m][0];
    const float cy = g_center[b][m][1];
    const float cz = g_center[b][m][2];
    const float* __restrict__ px = g_xyzT[b][0];
    const float* __restrict__ py = g_xyzT[b][1];
    const float* __restrict__ pz = g_xyzT[b][2];

    int count = 0;
    for (int n0 = 0; n0 < N_PTS; n0 += 32) {
        int i = n0 + lane;
        float dx = px[i] - cx;
        float dy = py[i] - cy;
        float dz = pz[i] - cz;
        float d  = sqdist(dx, dy, dz);
        bool pr  = (d <= 0.16f);
        unsigned mask = __ballot_sync(0xffffffffu, pr);
        int pos = count + __popc(mask & ((1u << lane) - 1u));
        if (pr && pos < 32) buf[wid][pos] = i;
        count += __popc(mask);
        if (count >= 32) break;
    }
    __syncwarp();
    int first = buf[wid][0];
    int v = (lane < count) ? buf[wid][lane] : first;
    g_ball[b][m][lane] = v;
}

// ======================= fused MLP + maxpool (R2 mapping) =======================
#define STR 65
#define OFF_XS  0
#define OFF_H1  (OFF_XS + 72 * STR)
#define OFF_H2  (OFF_H1 + 64 * STR)
#define OFF_WS  (OFF_H2 + 128 * STR)
#define OFF_SIDX (OFF_WS + 8 * 256)
#define OFF_SCTR (OFF_SIDX + 64)
#define MLP_SMEM_FLOATS (OFF_SCTR + 8)

template <int CIN, int COUT, bool LAST>
__device__ __forceinline__ void mlp_layer(
    const float* __restrict__ Wt,
    const float* __restrict__ bias,
    const float* __restrict__ scale,
    const float* __restrict__ shift,
    const float* Xin, float* Xout, float* Ws,
    float* __restrict__ outF, int b, int m0)
{
    const int tid = threadIdx.x;
    const int kk  = tid & 7;
    const int ro  = tid >> 3;
    constexpr int R = COUT / 32;

    float acc[R][8];
#pragma unroll
    for (int i = 0; i < R; ++i)
#pragma unroll
        for (int j = 0; j < 8; ++j) acc[i][j] = 0.0f;

    for (int ct = 0; ct < CIN; ct += 8) {
        __syncthreads();
        for (int e = tid; e < 8 * COUT; e += 256) Ws[e] = Wt[ct * COUT + e];
        __syncthreads();
#pragma unroll
        for (int cl = 0; cl < 8; ++cl) {
            float xv[8];
#pragma unroll
            for (int j = 0; j < 8; ++j) xv[j] = Xin[(ct + cl) * STR + kk + 8 * j];
#pragma unroll
            for (int i = 0; i < R; ++i) {
                float wv = Ws[cl * COUT + ro + 32 * i];
#pragma unroll
                for (int j = 0; j < 8; ++j) acc[i][j] = fmaf(wv, xv[j], acc[i][j]);
            }
        }
    }
    __syncthreads();

#pragma unroll
    for (int i = 0; i < R; ++i) {
        int o = ro + 32 * i;
        float bb = bias[o], ss = scale[o], tt = shift[o];
        if constexpr (!LAST) {
#pragma unroll
            for (int j = 0; j < 8; ++j) {
                float v = (acc[i][j] + bb) * ss + tt;
                Xout[o * STR + kk + 8 * j] = fmaxf(v, 0.0f);
            }
        } else {
            float vA = 0.0f, vB = 0.0f;
#pragma unroll
            for (int j = 0; j < 8; ++j) {
                float v = fmaxf((acc[i][j] + bb) * ss + tt, 0.0f);
                if (j < 4) vA = fmaxf(vA, v); else vB = fmaxf(vB, v);
            }
#pragma unroll
            for (int d = 1; d < 8; d <<= 1) {
                vA = fmaxf(vA, __shfl_xor_sync(0xffffffffu, vA, d));
                vB = fmaxf(vB, __shfl_xor_sync(0xffffffffu, vB, d));
            }
            if (kk == 0) {
                outF[(b * 256 + o) * M_PTS + m0]     = vA;
                outF[(b * 256 + o) * M_PTS + m0 + 1] = vB;
            }
        }
    }
    if constexpr (!LAST) __syncthreads();
}

__global__ __launch_bounds__(256, 2) void mlp_kernel(
    const float* __restrict__ b0, const float* __restrict__ s0, const float* __restrict__ t0,
    const float* __restrict__ b1, const float* __restrict__ s1, const float* __restrict__ t1,
    const float* __restrict__ b2, const float* __restrict__ s2, const float* __restrict__ t2,
    float* __restrict__ outF)
{
    extern __shared__ float sm[];
    const int tid = threadIdx.x;
    const int b   = blockIdx.y;
    const int m0  = blockIdx.x * 2;

    int*   sIdx = (int*)(sm + OFF_SIDX);
    float* sCtr = sm + OFF_SCTR;

    if (tid < 64) sIdx[tid] = g_ball[b][m0 + (tid >> 5)][tid & 31];
    if (tid < 6)  sCtr[tid] = g_center[b][m0 + tid / 3][tid % 3];
    __syncthreads();

    {
        int col  = tid >> 2;
        int part = tid & 3;
        int p    = sIdx[col];
        int half = col >> 5;
        float cx = sCtr[half * 3 + 0];
        float cy = sCtr[half * 3 + 1];
        float cz = sCtr[half * 3 + 2];
        const float* fp = &g_featT[b][p][0];
#pragma unroll
        for (int jj = 0; jj < 18; ++jj) {
            int r = part * 18 + jj;
            float v;
            if (r == 0)      v = g_xyzT[b][0][p] - cx;
            else if (r == 1) v = g_xyzT[b][1][p] - cy;
            else if (r == 2) v = g_xyzT[b][2][p] - cz;
            else if (r < 67) v = fp[r - 3];
            else             v = 0.0f;
            sm[OFF_XS + r * STR + col] = v;
        }
    }
    __syncthreads();

    mlp_layer<72, 64, false>(g_Wt0, b0, s0, t0, sm + OFF_XS, sm + OFF_H1, sm + OFF_WS, nullptr, b, m0);
    mlp_layer<64, 128, false>(g_Wt1, b1, s1, t1, sm + OFF_H1, sm + OFF_H2, sm + OFF_WS, nullptr, b, m0);
    mlp_layer<128, 256, true>(g_Wt2, b2, s2, t2, sm + OFF_H2, nullptr,     sm + OFF_WS, outF, b, m0);
}

// ======================= launch =======================
extern "C" void kernel_launch(void* const* d_in, const int* in_sizes, int n_in,
                              void* d_out, int out_size) {
    const float* xyz  = (const float*)d_in[0];
    const float* feat = (const float*)d_in[1];
    const float* W0 = (const float*)d_in[2];
    const float* b0 = (const float*)d_in[3];
    const float* s0 = (const float*)d_in[4];
    const float* t0 = (const float*)d_in[5];
    const float* W1 = (const float*)d_in[6];
    const float* b1 = (const float*)d_in[7];
    const float* s1 = (const float*)d_in[8];
    const float* t1 = (const float*)d_in[9];
    const float* W2 = (const float*)d_in[10];
    const float* b2 = (const float*)d_in[11];
    const float* s2 = (const float*)d_in[12];
    const float* t2 = (const float*)d_in[13];
    float* out = (float*)d_out;

    const int fps_smem = (3 * N_PTS + 128) * sizeof(float);
    const int mlp_smem = MLP_SMEM_FLOATS * sizeof(float);
    cudaFuncSetAttribute(fps_kernel, cudaFuncAttributeMaxDynamicSharedMemorySize, fps_smem);
    cudaFuncSetAttribute(mlp_kernel, cudaFuncAttributeMaxDynamicSharedMemorySize, mlp_smem);

    prep_w_kernel<<<178, 256>>>(W0, W1, W2);
    prep_xyz_kernel<<<1536, 256>>>(xyz);
    prep_feat_kernel<<<dim3(N_PTS / 32, CFEAT / 32, BATCH), dim3(32, 8)>>>(feat);

    fps_kernel<<<BATCH, 1024, fps_smem>>>(xyz, out);
    ball_kernel<<<(BATCH * M_PTS) / 4, 128>>>();
    mlp_kernel<<<dim3(M_PTS / 2, BATCH), 256, mlp_smem>>>(
        b0, s0, t0, b1, s1, t1, b2, s2, t2, out + OUT_FEAT_OFF);
}